// round 5
// baseline (speedup 1.0000x reference)
#include <cuda_runtime.h>
#include <cuda_bf16.h>

#define N_PRED        1024
#define M_GT          2048
#define P             20
#define THREADS       256
#define PREDS_PER_BLK 4
#define SLICES        4
#define SLICE_M       (M_GT / SLICES)       // 512
#define ROWS_PER_T    (SLICE_M / THREADS)   // 2
#define N_GROUPS      (N_PRED / PREDS_PER_BLK) // 256

typedef unsigned long long u64;

// Cross-kernel scratch (static device globals: allocation-free, graph-safe).
__device__ float g_part_min[N_PRED * SLICES];
__device__ int   g_part_idx[N_PRED * SLICES];

__device__ __forceinline__ float fsqrt_approx(float x) {
    float r;
    asm("sqrt.approx.f32 %0, %1;" : "=f"(r) : "f"(x));
    return r;
}
__device__ __forceinline__ u64 pack2(float lo, float hi) {
    u64 r;
    asm("mov.b64 %0, {%1, %2};"
        : "=l"(r) : "r"(__float_as_uint(lo)), "r"(__float_as_uint(hi)));
    return r;
}
__device__ __forceinline__ void unpack2(u64 v, float& lo, float& hi) {
    unsigned a, b;
    asm("mov.b64 {%0, %1}, %2;" : "=r"(a), "=r"(b) : "l"(v));
    lo = __uint_as_float(a);
    hi = __uint_as_float(b);
}
__device__ __forceinline__ u64 add2(u64 a, u64 b) {
    u64 r; asm("add.rn.f32x2 %0, %1, %2;" : "=l"(r) : "l"(a), "l"(b)); return r;
}
__device__ __forceinline__ u64 mul2(u64 a, u64 b) {
    u64 r; asm("mul.rn.f32x2 %0, %1, %2;" : "=l"(r) : "l"(a), "l"(b)); return r;
}
__device__ __forceinline__ u64 fma2(u64 a, u64 b, u64 c) {
    u64 r; asm("fma.rn.f32x2 %0, %1, %2, %3;" : "=l"(r) : "l"(a), "l"(b), "l"(c)); return r;
}
__device__ __forceinline__ float rsqrt_seed(float x) {
    unsigned i = __float_as_uint(x);
    i = 0x5f3759dfu - (i >> 1);
    return __uint_as_float(i);
}

// Kernel 1: each block = 4 pred rows x one 512-row gt slice.
// Grid is slice-major (blocks 0..255 all work on slice 0) so concurrently
// resident blocks hit the same gt lines in L2.
__global__ __launch_bounds__(THREADS)
void pm_partial_kernel(const float* __restrict__ pred,
                       const float* __restrict__ gt) {
    const int bx    = blockIdx.x;
    const int slice = bx / N_GROUPS;     // 0..3
    const int group = bx % N_GROUPS;     // 0..255
    const int tid   = threadIdx.x;

    // Pred rows for this block, pre-negated + lane-packed, in shared memory.
    // s_np[p][i] = { (-x0,-x1), (-y0,-y1) } for pred point-pair i.
    __shared__ __align__(16) u64 s_np[PREDS_PER_BLK][10][2];
    __shared__ float s_min[PREDS_PER_BLK][THREADS];
    __shared__ int   s_idx[PREDS_PER_BLK][THREADS];

    if (tid < PREDS_PER_BLK * 10) {
        const int p = tid / 10;
        const int i = tid % 10;
        const float4 pv = reinterpret_cast<const float4*>(pred)
                              [(group * PREDS_PER_BLK + p) * 10 + i];
        s_np[p][i][0] = pack2(-pv.x, -pv.z);
        s_np[p][i][1] = pack2(-pv.y, -pv.w);
    }
    __syncthreads();

    const u64 c_neg_half = pack2(-0.5f, -0.5f);
    const u64 c_1p5      = pack2(1.5f, 1.5f);

    float best[PREDS_PER_BLK];
    int   bestm[PREDS_PER_BLK];
#pragma unroll
    for (int p = 0; p < PREDS_PER_BLK; p++) { best[p] = 3.4e38f; bestm[p] = 0; }

#pragma unroll
    for (int j = 0; j < ROWS_PER_T; j++) {
        const int m = slice * SLICE_M + j * THREADS + tid;  // coalesced, ascending
        const float4* gr = reinterpret_cast<const float4*>(gt + m * (P * 2));

        u64 acc[PREDS_PER_BLK];
#pragma unroll
        for (int p = 0; p < PREDS_PER_BLK; p++) acc[p] = 0;

#pragma unroll
        for (int i = 0; i < 10; i++) {
            const float4 g = gr[i];
            const u64 gx = pack2(g.x, g.z);
            const u64 gy = pack2(g.y, g.w);
#pragma unroll
            for (int p = 0; p < PREDS_PER_BLK; p++) {
                const u64 dx = add2(gx, s_np[p][i][0]);   // g - pred (x lanes)
                const u64 dy = add2(gy, s_np[p][i][1]);   // g - pred (y lanes)
                const u64 s  = fma2(dy, dy, mul2(dx, dx));
                if (i == 0 || i == 5) {
                    // FMA-pipe sqrt (offloads 20% of sqrts from MUFU):
                    // magic rsqrt seed + 3 Newton iterations -> ~1e-7 rel err.
                    float s0, s1;
                    unpack2(s, s0, s1);
                    s0 = fmaxf(s0, 1e-35f);
                    s1 = fmaxf(s1, 1e-35f);
                    const u64 sc  = pack2(s0, s1);
                    u64 r   = pack2(rsqrt_seed(s0), rsqrt_seed(s1));
                    const u64 nxh = mul2(sc, c_neg_half);
                    r = mul2(r, fma2(nxh, mul2(r, r), c_1p5));
                    r = mul2(r, fma2(nxh, mul2(r, r), c_1p5));
                    r = mul2(r, fma2(nxh, mul2(r, r), c_1p5));
                    acc[p] = add2(acc[p], mul2(sc, r));
                } else {
                    float s0, s1;
                    unpack2(s, s0, s1);
                    acc[p] = add2(acc[p], pack2(fsqrt_approx(s0), fsqrt_approx(s1)));
                }
            }
        }

#pragma unroll
        for (int p = 0; p < PREDS_PER_BLK; p++) {
            float a0, a1;
            unpack2(acc[p], a0, a1);
            const float sum = a0 + a1;
            // m ascends within thread; strict < keeps the first (smallest) m.
            if (sum < best[p]) { best[p] = sum; bestm[p] = m; }
        }
    }

    // Block min+argmin reduction per pred, smaller-index tie-break.
#pragma unroll
    for (int p = 0; p < PREDS_PER_BLK; p++) {
        s_min[p][tid] = best[p];
        s_idx[p][tid] = bestm[p];
    }
    __syncthreads();
#pragma unroll
    for (int s = THREADS / 2; s > 0; s >>= 1) {
        if (tid < s) {
#pragma unroll
            for (int p = 0; p < PREDS_PER_BLK; p++) {
                const float o  = s_min[p][tid + s];
                const int   oi = s_idx[p][tid + s];
                const float c  = s_min[p][tid];
                const int   ci = s_idx[p][tid];
                if (o < c || (o == c && oi < ci)) {
                    s_min[p][tid] = o;
                    s_idx[p][tid] = oi;
                }
            }
        }
        __syncthreads();
    }

    if (tid < PREDS_PER_BLK) {
        const int n = group * PREDS_PER_BLK + tid;
        g_part_min[n * SLICES + slice] = s_min[tid][0];
        g_part_idx[n * SLICES + slice] = s_idx[tid][0];
    }
}

// Kernel 2: combine slice partials, write confidence/indices, gather points.
__global__ __launch_bounds__(THREADS)
void pm_finalize_kernel(const float* __restrict__ gt,
                        float* __restrict__ out_points,
                        float* __restrict__ out_conf,
                        float* __restrict__ out_idx) {
    const int n = blockIdx.x * THREADS + threadIdx.x;
    if (n >= N_PRED) return;

    float bm = 3.4e38f;
    int   bi = 0;
    // Slices partition m in ascending order; ascending scan with strict <
    // keeps the smallest index on exact ties.
#pragma unroll
    for (int s = 0; s < SLICES; s++) {
        const float v = g_part_min[n * SLICES + s];
        if (v < bm) { bm = v; bi = g_part_idx[n * SLICES + s]; }
    }

    const float md = bm * (1.0f / (float)P);   // mean distance

    const float4* gb = reinterpret_cast<const float4*>(gt + bi * (P * 2));
    float4* op = reinterpret_cast<float4*>(out_points + n * (P * 2));
#pragma unroll
    for (int i = 0; i < 10; i++) op[i] = gb[i];

    const float conf = (md > 2.0f) ? 0.0f : __expf(-md);
    out_conf[n] = conf;
    out_idx[n]  = (float)bi;
}

extern "C" void kernel_launch(void* const* d_in, const int* in_sizes, int n_in,
                              void* d_out, int out_size) {
    const float* pred = (const float*)d_in[0];   // (1024, 20, 2) f32
    const float* gt   = (const float*)d_in[1];   // (2048, 20, 2) f32
    float* out = (float*)d_out;

    // Output layout (validated R4): points | confidence | indices (as f32).
    float* out_points = out;
    float* out_conf   = out + N_PRED * P * 2;
    float* out_idx    = out + N_PRED * P * 2 + N_PRED;

    pm_partial_kernel<<<N_GROUPS * SLICES, THREADS>>>(pred, gt);
    pm_finalize_kernel<<<(N_PRED + THREADS - 1) / THREADS, THREADS>>>(
        gt, out_points, out_conf, out_idx);
}

// round 7
// speedup vs baseline: 1.0555x; 1.0555x over previous
#include <cuda_runtime.h>
#include <cuda_bf16.h>

#define N_PRED   1024
#define M_GT     2048
#define P        20
#define THREADS  256
#define M_PER_T  (M_GT / THREADS)   // 8
#define WARPS    (THREADS / 32)     // 8

typedef unsigned long long u64;

__device__ __forceinline__ float fsqrt_approx(float x) {
    float r;
    asm("sqrt.approx.f32 %0, %1;" : "=f"(r) : "f"(x));
    return r;
}
__device__ __forceinline__ u64 pack2(float lo, float hi) {
    u64 r;
    asm("mov.b64 %0, {%1, %2};"
        : "=l"(r) : "r"(__float_as_uint(lo)), "r"(__float_as_uint(hi)));
    return r;
}
__device__ __forceinline__ void unpack2(u64 v, float& lo, float& hi) {
    unsigned a, b;
    asm("mov.b64 {%0, %1}, %2;" : "=r"(a), "=r"(b) : "l"(v));
    lo = __uint_as_float(a);
    hi = __uint_as_float(b);
}
__device__ __forceinline__ u64 add2(u64 a, u64 b) {
    u64 r; asm("add.rn.f32x2 %0, %1, %2;" : "=l"(r) : "l"(a), "l"(b)); return r;
}
__device__ __forceinline__ u64 mul2(u64 a, u64 b) {
    u64 r; asm("mul.rn.f32x2 %0, %1, %2;" : "=l"(r) : "l"(a), "l"(b)); return r;
}
__device__ __forceinline__ u64 fma2(u64 a, u64 b, u64 c) {
    u64 r; asm("fma.rn.f32x2 %0, %1, %2, %3;" : "=l"(r) : "l"(a), "l"(b), "l"(c)); return r;
}

// Forcing 8 blocks/SM (regs <= 32) puts all 1024 blocks chip-resident in a
// single wave: no straggler wave, max warps for latency hiding.
__global__ __launch_bounds__(THREADS, 8)
void PointMatcher_29437705847326_kernel(const float* __restrict__ pred,
                                        const float* __restrict__ gt,
                                        float* __restrict__ out_points,
                                        float* __restrict__ out_conf,
                                        float* __restrict__ out_idx) {
    const int n   = blockIdx.x;
    const int tid = threadIdx.x;

    // Pred row, negated + lane-packed, in shared memory (keeps regs low;
    // LDS broadcasts replace per-thread global rematerialization).
    // s_np[i][0] = (-x0,-x1), s_np[i][1] = (-y0,-y1) for point-pair i.
    __shared__ __align__(16) u64 s_np[10][2];
    __shared__ float s_wmin[WARPS];
    __shared__ int   s_widx[WARPS];
    __shared__ int   s_best;

    if (tid < 10) {
        const float4 pv = reinterpret_cast<const float4*>(pred)[n * 10 + tid];
        s_np[tid][0] = pack2(-pv.x, -pv.z);
        s_np[tid][1] = pack2(-pv.y, -pv.w);
    }
    __syncthreads();

    float best  = 3.4e38f;
    int   bestm = 0;

#pragma unroll 2
    for (int j = 0; j < M_PER_T; j++) {
        const int m = j * THREADS + tid;           // coalesced, ascending in j
        const float4* gr = reinterpret_cast<const float4*>(gt + m * (P * 2));
        u64 acc2 = 0;                              // packed (0.0f, 0.0f)
#pragma unroll
        for (int i = 0; i < 10; i++) {
            const float4 g = gr[i];
            const u64 gx = pack2(g.x, g.z);
            const u64 gy = pack2(g.y, g.w);
            const u64 dx = add2(gx, s_np[i][0]);   // g - pred (x lanes)
            const u64 dy = add2(gy, s_np[i][1]);   // g - pred (y lanes)
            const u64 s  = fma2(dy, dy, mul2(dx, dx));
            float s0, s1;
            unpack2(s, s0, s1);
            acc2 = add2(acc2, pack2(fsqrt_approx(s0), fsqrt_approx(s1)));
        }
        float a0, a1;
        unpack2(acc2, a0, a1);
        const float sum = a0 + a1;
        // m ascends within a thread; strict < keeps the first (smallest) m.
        if (sum < best) { best = sum; bestm = m; }
    }

    // Warp min+argmin (smaller-index tie-break), then combine 8 warp partials.
#pragma unroll
    for (int off = 16; off > 0; off >>= 1) {
        const float o  = __shfl_down_sync(0xffffffffu, best, off);
        const int   oi = __shfl_down_sync(0xffffffffu, bestm, off);
        if (o < best || (o == best && oi < bestm)) { best = o; bestm = oi; }
    }
    if ((tid & 31) == 0) {
        s_wmin[tid >> 5] = best;
        s_widx[tid >> 5] = bestm;
    }
    __syncthreads();

    if (tid == 0) {
        float bm = s_wmin[0];
        int   bi = s_widx[0];
#pragma unroll
        for (int w = 1; w < WARPS; w++) {
            const float v = s_wmin[w];
            const int   vi = s_widx[w];
            if (v < bm || (v == bm && vi < bi)) { bm = v; bi = vi; }
        }
        s_best = bi;
        const float md = bm * (1.0f / (float)P);   // mean distance
        const float conf = (md > 2.0f) ? 0.0f : __expf(-md);
        out_conf[n] = conf;
        out_idx[n]  = (float)bi;
    }
    __syncthreads();

    // Gather matched gt row -> out_points[n]
    if (tid < 10) {
        const float4 gb = reinterpret_cast<const float4*>(gt)[s_best * 10 + tid];
        reinterpret_cast<float4*>(out_points + n * (P * 2))[tid] = gb;
    }
}

extern "C" void kernel_launch(void* const* d_in, const int* in_sizes, int n_in,
                              void* d_out, int out_size) {
    const float* pred = (const float*)d_in[0];   // (1024, 20, 2) f32
    const float* gt   = (const float*)d_in[1];   // (2048, 20, 2) f32
    float* out = (float*)d_out;

    // Output layout (validated R4): points | confidence | indices (as f32).
    float* out_points = out;
    float* out_conf   = out + N_PRED * P * 2;
    float* out_idx    = out + N_PRED * P * 2 + N_PRED;

    PointMatcher_29437705847326_kernel<<<N_PRED, THREADS>>>(
        pred, gt, out_points, out_conf, out_idx);
}

// round 8
// speedup vs baseline: 1.1469x; 1.0866x over previous
#include <cuda_runtime.h>
#include <cuda_bf16.h>

#define N_PRED   1024
#define M_GT     2048
#define P        20
#define THREADS  256
#define M_PER_T  (M_GT / THREADS)   // 8
#define WARPS    (THREADS / 32)     // 8

typedef unsigned long long u64;

__device__ __forceinline__ float fsqrt_approx(float x) {
    float r;
    asm("sqrt.approx.f32 %0, %1;" : "=f"(r) : "f"(x));
    return r;
}
__device__ __forceinline__ u64 pack2(float lo, float hi) {
    u64 r;
    asm("mov.b64 %0, {%1, %2};"
        : "=l"(r) : "r"(__float_as_uint(lo)), "r"(__float_as_uint(hi)));
    return r;
}
__device__ __forceinline__ void unpack2(u64 v, float& lo, float& hi) {
    unsigned a, b;
    asm("mov.b64 {%0, %1}, %2;" : "=r"(a), "=r"(b) : "l"(v));
    lo = __uint_as_float(a);
    hi = __uint_as_float(b);
}
__device__ __forceinline__ u64 add2(u64 a, u64 b) {
    u64 r; asm("add.rn.f32x2 %0, %1, %2;" : "=l"(r) : "l"(a), "l"(b)); return r;
}
__device__ __forceinline__ u64 mul2(u64 a, u64 b) {
    u64 r; asm("mul.rn.f32x2 %0, %1, %2;" : "=l"(r) : "l"(a), "l"(b)); return r;
}
__device__ __forceinline__ u64 fma2(u64 a, u64 b, u64 c) {
    u64 r; asm("fma.rn.f32x2 %0, %1, %2, %3;" : "=l"(r) : "l"(a), "l"(b), "l"(c)); return r;
}
// Magic inverse-sqrt seed (ALU pipe: shift+sub per lane).
__device__ __forceinline__ float rsqrt_seed(float x) {
    unsigned i = __float_as_uint(x);
    i = 0x5f3759dfu - (i >> 1);
    return __uint_as_float(i);
}

__global__ __launch_bounds__(THREADS)
void PointMatcher_29437705847326_kernel(const float* __restrict__ pred,
                                        const float* __restrict__ gt,
                                        float* __restrict__ out_points,
                                        float* __restrict__ out_conf,
                                        float* __restrict__ out_idx) {
    const int n   = blockIdx.x;
    const int tid = threadIdx.x;

    // Pred row, negated + lane-packed, in shared memory.
    __shared__ __align__(16) u64 s_np[10][2];
    __shared__ float s_wmin[WARPS];
    __shared__ int   s_widx[WARPS];
    __shared__ int   s_best;

    if (tid < 10) {
        const float4 pv = reinterpret_cast<const float4*>(pred)[n * 10 + tid];
        s_np[tid][0] = pack2(-pv.x, -pv.z);
        s_np[tid][1] = pack2(-pv.y, -pv.w);
    }
    __syncthreads();

    const u64 c_neg_half = pack2(-0.5f, -0.5f);
    const u64 c_1p5      = pack2(1.5f, 1.5f);

    float best  = 3.4e38f;
    int   bestm = 0;

#pragma unroll 2
    for (int j = 0; j < M_PER_T; j++) {
        const int m = j * THREADS + tid;           // coalesced, ascending in j
        const float4* gr = reinterpret_cast<const float4*>(gt + m * (P * 2));
        u64 acc_mufu = 0;                          // MUFU-path accumulator
        u64 acc_fma  = 0;                          // Newton-path accumulator
#pragma unroll
        for (int i = 0; i < 10; i++) {
            const float4 g = gr[i];
            const u64 gx = pack2(g.x, g.z);
            const u64 gy = pack2(g.y, g.w);
            const u64 dx = add2(gx, s_np[i][0]);   // g - pred (x lanes)
            const u64 dy = add2(gy, s_np[i][1]);   // g - pred (y lanes)
            const u64 s  = fma2(dy, dy, mul2(dx, dx));
            if (i & 1) {
                // FMA-pipe sqrt: magic rsqrt seed + 3 packed Newton iters
                // (rel err ~1e-7, matches MUFU path). Offloads 40% of the
                // sqrt stream from the ~76%-busy MUFU pipe to the 15%-busy
                // FMA pipe. s == 0 is benign: nxh = 0 keeps r finite and
                // s * r = 0.
                float s0, s1;
                unpack2(s, s0, s1);
                u64 r = pack2(rsqrt_seed(s0), rsqrt_seed(s1));
                const u64 nxh = mul2(s, c_neg_half);
                r = mul2(r, fma2(nxh, mul2(r, r), c_1p5));
                r = mul2(r, fma2(nxh, mul2(r, r), c_1p5));
                r = mul2(r, fma2(nxh, mul2(r, r), c_1p5));
                acc_fma = add2(acc_fma, mul2(s, r));
            } else {
                float s0, s1;
                unpack2(s, s0, s1);
                acc_mufu = add2(acc_mufu,
                                pack2(fsqrt_approx(s0), fsqrt_approx(s1)));
            }
        }
        const u64 acc2 = add2(acc_mufu, acc_fma);
        float a0, a1;
        unpack2(acc2, a0, a1);
        const float sum = a0 + a1;
        // m ascends within a thread; strict < keeps the first (smallest) m.
        if (sum < best) { best = sum; bestm = m; }
    }

    // Warp min+argmin (smaller-index tie-break), then combine 8 warp partials.
#pragma unroll
    for (int off = 16; off > 0; off >>= 1) {
        const float o  = __shfl_down_sync(0xffffffffu, best, off);
        const int   oi = __shfl_down_sync(0xffffffffu, bestm, off);
        if (o < best || (o == best && oi < bestm)) { best = o; bestm = oi; }
    }
    if ((tid & 31) == 0) {
        s_wmin[tid >> 5] = best;
        s_widx[tid >> 5] = bestm;
    }
    __syncthreads();

    if (tid == 0) {
        float bm = s_wmin[0];
        int   bi = s_widx[0];
#pragma unroll
        for (int w = 1; w < WARPS; w++) {
            const float v = s_wmin[w];
            const int   vi = s_widx[w];
            if (v < bm || (v == bm && vi < bi)) { bm = v; bi = vi; }
        }
        s_best = bi;
        const float md = bm * (1.0f / (float)P);   // mean distance
        const float conf = (md > 2.0f) ? 0.0f : __expf(-md);
        out_conf[n] = conf;
        out_idx[n]  = (float)bi;
    }
    __syncthreads();

    // Gather matched gt row -> out_points[n]
    if (tid < 10) {
        const float4 gb = reinterpret_cast<const float4*>(gt)[s_best * 10 + tid];
        reinterpret_cast<float4*>(out_points + n * (P * 2))[tid] = gb;
    }
}

extern "C" void kernel_launch(void* const* d_in, const int* in_sizes, int n_in,
                              void* d_out, int out_size) {
    const float* pred = (const float*)d_in[0];   // (1024, 20, 2) f32
    const float* gt   = (const float*)d_in[1];   // (2048, 20, 2) f32
    float* out = (float*)d_out;

    // Output layout (validated R4): points | confidence | indices (as f32).
    float* out_points = out;
    float* out_conf   = out + N_PRED * P * 2;
    float* out_idx    = out + N_PRED * P * 2 + N_PRED;

    PointMatcher_29437705847326_kernel<<<N_PRED, THREADS>>>(
        pred, gt, out_points, out_conf, out_idx);
}